// round 1
// baseline (speedup 1.0000x reference)
#include <cuda_runtime.h>

#define BATCH 4
#define M 4096          // points per cloud (both x and y)
#define NC 4            // chunks of the "min-over" dimension
#define CHUNK (M / NC)  // 1024
#define TX 128          // threads per block == x-points per block
#define XT (M / TX)     // 32 x-tiles

// scratch: partial min of squared distance, [dir][batch][chunk][x]
__device__ float g_partial[2 * BATCH * NC * M];

__global__ void chamfer_partial(const float* __restrict__ x,
                                const float* __restrict__ y) {
    // decode block index: [batch][xt][chunk][dir]
    int bid = blockIdx.x;
    int dir = bid & 1;        bid >>= 1;
    int c   = bid & (NC - 1); bid >>= 2;
    int xt  = bid & (XT - 1); bid >>= 5;
    int bb  = bid;

    const float* A  = dir ? y : x;  // take min FOR these points
    const float* Bp = dir ? x : y;  // min OVER these points

    __shared__ float4 sp[CHUNK];

    // cooperative load of the Bp chunk into smem, precomputing |p|^2
    const float* src = Bp + ((size_t)bb * M + (size_t)c * CHUNK) * 3;
    for (int p = threadIdx.x; p < CHUNK; p += TX) {
        float p0 = src[p * 3 + 0];
        float p1 = src[p * 3 + 1];
        float p2 = src[p * 3 + 2];
        sp[p] = make_float4(p0, p1, p2, p0 * p0 + p1 * p1 + p2 * p2);
    }
    __syncthreads();

    int xi = xt * TX + threadIdx.x;
    const float* ax = A + ((size_t)bb * M + xi) * 3;
    float x0 = ax[0], x1 = ax[1], x2 = ax[2];
    float sx = x0 * x0 + x1 * x1 + x2 * x2;
    float n0 = -2.0f * x0, n1 = -2.0f * x1, n2 = -2.0f * x2;

    // d^2 = sx + (|p|^2 - 2 x.p); track min of t = |p|^2 - 2 x.p
    // two accumulators to break the FMNMX dependency chain
    float m0 = 3.4e38f, m1 = 3.4e38f;
#pragma unroll 8
    for (int k = 0; k < CHUNK; k += 2) {
        float4 p = sp[k];
        float4 q = sp[k + 1];
        float t0 = fmaf(n0, p.x, fmaf(n1, p.y, fmaf(n2, p.z, p.w)));
        float t1 = fmaf(n0, q.x, fmaf(n1, q.y, fmaf(n2, q.z, q.w)));
        m0 = fminf(m0, t0);
        m1 = fminf(m1, t1);
    }

    g_partial[(((size_t)dir * BATCH + bb) * NC + c) * M + xi] =
        sx + fminf(m0, m1);
}

__global__ void chamfer_reduce(float* __restrict__ out) {
    int bb = blockIdx.x;
    float sum = 0.0f;

    for (int dir = 0; dir < 2; dir++) {
        const float* p = g_partial + ((size_t)dir * BATCH + bb) * NC * M;
        for (int xi = threadIdx.x; xi < M; xi += blockDim.x) {
            float v = p[xi];
#pragma unroll
            for (int c = 1; c < NC; c++) v = fminf(v, p[(size_t)c * M + xi]);
            sum += sqrtf(fmaxf(v, 0.0f));  // clamp: expansion can go slightly <0
        }
    }

    // block reduction
    __shared__ float red[32];
    for (int o = 16; o; o >>= 1) sum += __shfl_down_sync(0xffffffffu, sum, o);
    int w = threadIdx.x >> 5;
    if ((threadIdx.x & 31) == 0) red[w] = sum;
    __syncthreads();
    if (threadIdx.x < 32) {
        int nw = blockDim.x >> 5;
        float s = (threadIdx.x < nw) ? red[threadIdx.x] : 0.0f;
        for (int o = 16; o; o >>= 1) s += __shfl_down_sync(0xffffffffu, s, o);
        if (threadIdx.x == 0) out[bb] = s * (1.0f / (float)M);
    }
}

extern "C" void kernel_launch(void* const* d_in, const int* in_sizes, int n_in,
                              void* d_out, int out_size) {
    const float* x = (const float*)d_in[0];
    const float* y = (const float*)d_in[1];
    float* out = (float*)d_out;

    chamfer_partial<<<2 * BATCH * NC * XT, TX>>>(x, y);
    chamfer_reduce<<<BATCH, 256>>>(out);
}

// round 3
// speedup vs baseline: 1.0970x; 1.0970x over previous
#include <cuda_runtime.h>
#include <cfloat>

#define BATCH 4
#define M 4096
#define TX 128
#define XT (M / TX)          // 32 x-tiles per (dir, batch)
#define NB (2 * BATCH * XT)  // 256 blocks
#define HP (M / 2)           // 2048 packed y-point pairs
#define SMEM_BYTES (HP * 4 * 8)  // 64 KB

// per-block partial sums of sqrt(min d^2): [dir][batch][xt]
__device__ float g_bsums[NB];

// Packed fp32x2 helpers (Blackwell f32x2 pipe: 2 FMA lanes per instruction)
#define FMA2(d, a, b, c) \
    asm("fma.rn.f32x2 %0, %1, %2, %3;" : "=l"(d) : "l"(a), "l"(b), "l"(c))
#define PACK2(d, lo, hi) \
    asm("mov.b64 %0, {%1, %2};" : "=l"(d) : "f"(lo), "f"(hi))
#define UNPACK2(lo, hi, d) \
    asm("mov.b64 {%0, %1}, %2;" : "=f"(lo), "=f"(hi) : "l"(d))

__global__ __launch_bounds__(TX) void chamfer_main(const float* __restrict__ x,
                                                   const float* __restrict__ y) {
    int bid = blockIdx.x;
    int xt  = bid % XT;
    int bb  = (bid / XT) % BATCH;
    int dir = bid / (XT * BATCH);

    const float* A  = dir ? y : x;   // take min FOR these points
    const float* Bp = dir ? x : y;   // min OVER these points

    // smem: per pair j of y-points (2j, 2j+1): [x01, y01, z01, |p|^2_01]
    extern __shared__ unsigned long long sp[];

    const float2* src = (const float2*)(Bp + (size_t)bb * M * 3);
    for (int j = threadIdx.x; j < HP; j += TX) {
        float2 a = src[j * 3 + 0];
        float2 b = src[j * 3 + 1];
        float2 c = src[j * 3 + 2];
        // point0 = (a.x, a.y, b.x), point1 = (b.y, c.x, c.y)
        float w0 = fmaf(a.x, a.x, fmaf(a.y, a.y, b.x * b.x));
        float w1 = fmaf(b.y, b.y, fmaf(c.x, c.x, c.y * c.y));
        unsigned long long x01, y01, z01, w01;
        PACK2(x01, a.x, b.y);
        PACK2(y01, a.y, c.x);
        PACK2(z01, b.x, c.y);
        PACK2(w01, w0, w1);
        sp[j * 4 + 0] = x01;
        sp[j * 4 + 1] = y01;
        sp[j * 4 + 2] = z01;
        sp[j * 4 + 3] = w01;
    }
    __syncthreads();

    int xi = xt * TX + threadIdx.x;
    const float* ax = A + ((size_t)bb * M + xi) * 3;
    float x0 = ax[0], x1 = ax[1], x2 = ax[2];
    float sx = x0 * x0 + x1 * x1 + x2 * x2;
    float n0 = -2.0f * x0, n1 = -2.0f * x1, n2 = -2.0f * x2;
    unsigned long long n0_2, n1_2, n2_2;
    PACK2(n0_2, n0, n0);
    PACK2(n1_2, n1, n1);
    PACK2(n2_2, n2, n2);

    // d^2 = sx + (|p|^2 - 2 x.p); track min of t = |p|^2 - 2 x.p
    float m0 = FLT_MAX, m1 = FLT_MAX, m2 = FLT_MAX, m3 = FLT_MAX;
#pragma unroll 8
    for (int j = 0; j < HP; j++) {
        ulonglong2 v0 = *(const ulonglong2*)&sp[j * 4];      // x01, y01
        ulonglong2 v1 = *(const ulonglong2*)&sp[j * 4 + 2];  // z01, w01
        unsigned long long t;
        FMA2(t, n2_2, v1.x, v1.y);
        FMA2(t, n1_2, v0.y, t);
        FMA2(t, n0_2, v0.x, t);
        float lo, hi;
        UNPACK2(lo, hi, t);
        if (j & 1) {
            m2 = fminf(m2, lo);
            m3 = fminf(m3, hi);
        } else {
            m0 = fminf(m0, lo);
            m1 = fminf(m1, hi);
        }
    }

    float dmin = sx + fminf(fminf(m0, m1), fminf(m2, m3));
    float d = sqrtf(fmaxf(dmin, 0.0f));  // clamp: expansion can round < 0

    // block reduction: sum of d over TX threads
    __shared__ float red[TX / 32];
    for (int o = 16; o; o >>= 1) d += __shfl_down_sync(0xffffffffu, d, o);
    if ((threadIdx.x & 31) == 0) red[threadIdx.x >> 5] = d;
    __syncthreads();
    if (threadIdx.x == 0) {
        float s = 0.0f;
#pragma unroll
        for (int w = 0; w < TX / 32; w++) s += red[w];
        g_bsums[bid] = s;
    }
}

__global__ void chamfer_final(float* __restrict__ out) {
    int b = blockIdx.x;
    int t = threadIdx.x;  // 64 threads: 32 for dir0 tiles, 32 for dir1 tiles
    int idx = (t < 32) ? (b * XT + t) : (BATCH * XT + b * XT + (t - 32));
    float v = g_bsums[idx];
    for (int o = 16; o; o >>= 1) v += __shfl_down_sync(0xffffffffu, v, o);
    __shared__ float r2[2];
    if ((t & 31) == 0) r2[t >> 5] = v;
    __syncthreads();
    if (t == 0) out[b] = (r2[0] + r2[1]) * (1.0f / (float)M);
}

extern "C" void kernel_launch(void* const* d_in, const int* in_sizes, int n_in,
                              void* d_out, int out_size) {
    const float* x = (const float*)d_in[0];
    const float* y = (const float*)d_in[1];
    float* out = (float*)d_out;

    cudaFuncSetAttribute(chamfer_main,
                         cudaFuncAttributeMaxDynamicSharedMemorySize, SMEM_BYTES);
    chamfer_main<<<NB, TX, SMEM_BYTES>>>(x, y);
    chamfer_final<<<BATCH, 64>>>(out);
}